// round 6
// baseline (speedup 1.0000x reference)
#include <cuda_runtime.h>
#include <math.h>

#define BB 16
#define TT 50
#define AA 3
#define HH 76
#define WW 76
#define HWX 5776                    // 76*76
#define NCELL 277248                // BB*AA*HWX
#define NCLS 80
#define ATTR 85
#define NCH 255
#define PRED_B (NCH*HWX)
#define IGNORE_THR 0.5f
#define MAXIGN 160                  // per-batch ignore slots (worst case 121)

#define NV (NCELL/4)                            // 69312
#define DENSE_BLOCKS ((NV + 255)/256)           // 271
#define MASK_BLOCKS ((BB*TT*32 + 255)/256)      // 100
#define IGN_BLOCKS ((BB*MAXIGN + 255)/256)      // 10
#define TOTAL_BLOCKS (DENSE_BLOCKS + MASK_BLOCKS + IGN_BLOCKS)

__device__ __constant__ float c_aw[3] = {14.5f, 19.5f, 46.625f};
__device__ __constant__ float c_ah[3] = {11.25f, 24.75f, 40.75f};

__device__ int          g_rcell[BB*TT];
__device__ float        g_rtx[BB*TT], g_rty[BB*TT], g_rtw[BB*TT], g_rth[BB*TT];
__device__ unsigned int g_rtcls[BB*TT*3];
__device__ int          g_cnt[BB];
__device__ int          g_icell[BB*MAXIGN];
__device__ int          g_icnt[BB];
__device__ int          g_npos;
// g_acc: 0 = sum sp(conf) ALL cells, 1 = sum sp(conf) at ignore cells,
//        2 = masked obj terms (0.5*xy + 2.5*wh + conf_obj), 3 = cls sum
__device__ double       g_acc[4];

// sp(z) = log(1+e^z) = -log(1-sigmoid(z));  sp(-z) = -log(sigmoid(z))
__device__ __forceinline__ float sp(float z) {
    return (z > 15.0f) ? z : log1pf(expf(z));
}

__device__ __forceinline__ void blk_atomic(double v, double* dst) {
    #pragma unroll
    for (int o = 16; o; o >>= 1) v += __shfl_down_sync(0xffffffffu, v, o);
    __shared__ double sh[8];
    int lane = threadIdx.x & 31, wid = threadIdx.x >> 5;
    if (lane == 0) sh[wid] = v;
    __syncthreads();
    if (threadIdx.x == 0) {
        double t = 0.0;
        #pragma unroll
        for (int w = 0; w < 8; ++w) t += sh[w];
        if (t != 0.0) atomicAdd(dst, t);
    }
}

// ---------------- kernel 1: target encode (1 block, 32 threads) -------------
// JAX-wrap semantics: negative indices in the reference's scatter are wrapped
// (idx + size), NOT dropped. So:
//  * padded (all-zero) rows -> mask cell (b, anchor 0, j=0, i=WW-1),
//    tx=ty=0, tw=th=log(1e-16), class 0
//  * noobj scatter: anchors with iou<=thr wrap to anchor AA-1=2 -> ignore
//    cell (b, 2, gj, gi)  (padded rows -> (b,2,0,0))
__global__ void k_encode(const float* __restrict__ annot) {
    int b = threadIdx.x;
    if (b == 0) { g_acc[0]=0.0; g_acc[1]=0.0; g_acc[2]=0.0; g_acc[3]=0.0; }

    if (b < BB) {
        int   cells[TT];
        float ltx[TT], lty[TT], ltw[TT], lth[TT];
        unsigned int lcls[TT][3];
        int n = 0;
        int icell[MAXIGN];
        int icnt = 0;

        for (int t = 0; t < TT; ++t) {
            const float* an = annot + (b * TT + t) * 5;
            float a0 = an[0], a1 = an[1], a2 = an[2], a3 = an[3], a4 = an[4];
            bool valid = (a0 + a1 + a2 + a3 + a4) != 0.0f;

            float gx = a1 * (float)WW, gy = a2 * (float)HH;   // 0 if padded
            float gw = a3 * (float)WW, gh = a4 * (float)HH;
            int gi = (int)floorf(gx), gj = (int)floorf(gy);   // (0,0) if padded

            // IoU vs 3 anchors (all exactly 0 for padded rows -> best_n = 0)
            float ious[3];
            float best = -1.0f; int bn = 0;
            const float eps = 1e-9f;
            #pragma unroll
            for (int a = 0; a < 3; ++a) {
                float inter = fminf(gw, c_aw[a]) * fminf(gh, c_ah[a]);
                float un = gw * (gh + eps) + c_aw[a] * (c_ah[a] + eps) - inter + eps;
                float iou = inter / un;
                ious[a] = iou;
                if (iou > best) { best = iou; bn = a; }       // first max
            }

            // ignore cells with wrap: cond anchor a stays, !cond wraps to 2
            #pragma unroll
            for (int a = 0; a < 3; ++a) {
                bool cond = (ious[a] > IGNORE_THR) && valid;
                int ae = cond ? a : (AA - 1);
                int c = ((b * AA + ae) * HH + gj) * WW + gi;
                bool f = false;
                for (int q = 0; q < icnt; ++q) if (icell[q] == c) { f = true; break; }
                if (!f && icnt < MAXIGN) icell[icnt++] = c;
            }

            // mask scatter: gi_d = valid ? gi : -1 -> wrapped to WW-1
            int ii = valid ? gi : (WW - 1);
            if (ii < 0 || ii >= WW || gj < 0 || gj >= HH) continue;  // true OOB drops

            int cell = ((b * AA + bn) * HH + gj) * WW + ii;
            int k = -1;
            for (int q = 0; q < n; ++q) if (cells[q] == cell) { k = q; break; }
            if (k < 0) {
                k = n++;
                cells[k] = cell;
                lcls[k][0] = 0u; lcls[k][1] = 0u; lcls[k][2] = 0u;
            }
            ltx[k] = gx - (float)gi;                     // 0 for padded
            lty[k] = gy - (float)gj;
            ltw[k] = logf(gw / c_aw[bn] + 1e-16f);       // log(1e-16) for padded
            lth[k] = logf(gh / c_ah[bn] + 1e-16f);
            int ci = (int)a0;                            // 0 for padded
            if (ci >= 0 && ci < NCLS) lcls[k][ci >> 5] |= (1u << (ci & 31));
        }

        g_cnt[b] = n;
        for (int k = 0; k < n; ++k) {
            int s = b * TT + k;
            g_rcell[s] = cells[k];
            g_rtx[s] = ltx[k]; g_rty[s] = lty[k];
            g_rtw[s] = ltw[k]; g_rth[s] = lth[k];
            g_rtcls[s*3+0] = lcls[k][0];
            g_rtcls[s*3+1] = lcls[k][1];
            g_rtcls[s*3+2] = lcls[k][2];
        }
        g_icnt[b] = icnt;
        for (int k = 0; k < icnt; ++k) g_icell[b * MAXIGN + k] = icell[k];
    }
    __syncthreads();
    if (threadIdx.x == 0) {
        int np = 0;
        #pragma unroll
        for (int i = 0; i < BB; ++i) np += g_cnt[i];
        g_npos = np;
    }
}

// ---------------- kernel 2: fused reduce ------------------------------------
__global__ void k_main(const float* __restrict__ pred) {
    if (blockIdx.x < DENSE_BLOCKS) {
        // unconditional sum of sp(conf) over ALL cells -> g_acc[0]
        int tid = blockIdx.x * blockDim.x + threadIdx.x;
        double s = 0.0;
        if (tid < NV) {
            const int V_ROW = HWX / 4;                 // 1444
            int r = tid / V_ROW;
            int v = tid - r * V_ROW;
            int b = r / AA, a = r - b * AA;
            const float4 f = *reinterpret_cast<const float4*>(
                pred + (size_t)b * PRED_B + (size_t)(a * ATTR + 4) * HWX + 4 * v);
            s = (double)sp(f.x) + (double)sp(f.y) + (double)sp(f.z) + (double)sp(f.w);
        }
        blk_atomic(s, &g_acc[0]);
        return;
    }

    if (blockIdx.x < DENSE_BLOCKS + MASK_BLOCKS) {
        // one warp per mask record -> g_acc[2] (obj terms), g_acc[3] (cls sum)
        int widx = (blockIdx.x - DENSE_BLOCKS) * 8 + (threadIdx.x >> 5);
        int lane = threadIdx.x & 31;
        int b = widx / TT, k = widx - b * TT;
        double lcls = 0.0, lobj = 0.0;

        if (b < BB && k < g_cnt[b]) {
            int s = b * TT + k;
            int cell = g_rcell[s];
            int pix = cell % HWX;
            int a = (cell / HWX) % AA;
            const float* base = pred + (size_t)b * PRED_B + (size_t)(a * ATTR) * HWX;

            for (int c = lane; c < NCLS; c += 32) {
                float z = base[(size_t)(5 + c) * HWX + pix];
                bool tgt = (g_rtcls[s * 3 + (c >> 5)] >> (c & 31)) & 1u;
                lcls += (double)(tgt ? sp(-z) : sp(z));
            }
            if (lane == 0) {
                float zx = base[(size_t)0 * HWX + pix];
                float zy = base[(size_t)1 * HWX + pix];
                float zw = base[(size_t)2 * HWX + pix];
                float zh = base[(size_t)3 * HWX + pix];
                float zc = base[(size_t)4 * HWX + pix];
                float tx = g_rtx[s], ty = g_rty[s], tw = g_rtw[s], th = g_rth[s];
                double lxy = (double)(tx * sp(-zx) + (1.0f - tx) * sp(zx))
                           + (double)(ty * sp(-zy) + (1.0f - ty) * sp(zy));
                double lwh = (double)((zw - tw) * (zw - tw) + (zh - th) * (zh - th));
                lobj = 0.5 * lxy + 2.5 * lwh + (double)sp(-zc);
            }
        }
        blk_atomic(lcls, &g_acc[3]);
        __syncthreads();
        blk_atomic(lobj, &g_acc[2]);
        return;
    }

    // ignore cells: sum sp(conf) -> g_acc[1]
    {
        int j = (blockIdx.x - DENSE_BLOCKS - MASK_BLOCKS) * blockDim.x + threadIdx.x;
        int b = j / MAXIGN, k = j - b * MAXIGN;
        double s = 0.0;
        if (b < BB && k < g_icnt[b]) {
            int cell = g_icell[b * MAXIGN + k];
            int pix = cell % HWX;
            int a = (cell / HWX) % AA;
            s = (double)sp(pred[(size_t)b * PRED_B + (size_t)(a * ATTR + 4) * HWX + pix]);
        }
        blk_atomic(s, &g_acc[1]);
    }
}

// ---------------- kernel 3: finalize + broadcast -----------------------------
__global__ void k_fin(float* __restrict__ out, int n) {
    const double Nd = (double)NCELL;
    double loss = (0.5 * (g_acc[0] - g_acc[1]) + g_acc[2]) / Nd
                + g_acc[3] / ((double)g_npos * (double)NCLS);
    float v = (float)loss;
    for (int i = threadIdx.x; i < n; i += blockDim.x) out[i] = v;
}

extern "C" void kernel_launch(void* const* d_in, const int* in_sizes, int n_in,
                              void* d_out, int out_size) {
    // autodetect input order by element count (pred = 23.5M, annot = 4000)
    const float* pred;
    const float* annot;
    if (n_in >= 2 && in_sizes[1] > in_sizes[0]) {
        pred  = (const float*)d_in[1];
        annot = (const float*)d_in[0];
    } else {
        pred  = (const float*)d_in[0];
        annot = (const float*)d_in[1];
    }
    float* out = (float*)d_out;

    k_encode<<<1, 32>>>(annot);
    k_main<<<TOTAL_BLOCKS, 256>>>(pred);
    k_fin<<<1, 256>>>(out, out_size);
}

// round 7
// speedup vs baseline: 14.3007x; 14.3007x over previous
#include <cuda_runtime.h>
#include <math.h>

#define BB 16
#define TT 50
#define AA 3
#define HH 76
#define WW 76
#define HWX 5776                    // 76*76
#define NCELL 277248                // BB*AA*HWX
#define NCLS 80
#define ATTR 85
#define NCH 255
#define PRED_B (NCH*HWX)
#define IGNORE_THR 0.5f

#define NBITW ((NCELL + 31) / 32)   // 8664 bitmap words
#define TBL 2048
#define TBLM (TBL - 1)

#define NV (NCELL/4)                          // 69312 float4s of conf
#define DENSE_BLOCKS ((NV + 255)/256)         // 271
#define MASK_BLOCKS ((BB*TT + 7)/8)           // 100 blocks x 8 warps = 800 warps
#define TOTAL_BLOCKS (DENSE_BLOCKS + MASK_BLOCKS)

__device__ __constant__ float c_aw[3] = {14.5f, 19.5f, 46.625f};
__device__ __constant__ float c_ah[3] = {11.25f, 24.75f, 40.75f};

// ---------------- global scratch ----------------
__device__ unsigned int g_ign[NBITW];        // noobj-ignore bitmap (per cell)
__device__ int          g_rcell[TBL];
__device__ float        g_rtx[TBL], g_rty[TBL], g_rtw[TBL], g_rth[TBL];
__device__ unsigned int g_rtcls[TBL*3];
__device__ int          g_npos;
__device__ double       g_acc[3];            // 0: conf-noobj sum, 1: obj terms, 2: cls sum
__device__ unsigned int g_done;

// sp(z) = log(1+e^z) = -log(1-sigmoid(z));  sp(-z) = -log(sigmoid(z))
__device__ __forceinline__ float sp(float z) {
    return (z > 15.0f) ? z : log1pf(expf(z));
}

__device__ __forceinline__ void blk_atomic(double v, double* dst) {
    #pragma unroll
    for (int o = 16; o; o >>= 1) v += __shfl_down_sync(0xffffffffu, v, o);
    __shared__ double sh[8];
    int lane = threadIdx.x & 31, wid = threadIdx.x >> 5;
    if (lane == 0) sh[wid] = v;
    __syncthreads();
    if (threadIdx.x == 0) {
        double t = 0.0;
        #pragma unroll
        for (int w = 0; w < 8; ++w) t += sh[w];
        if (t != 0.0) atomicAdd(dst, t);
    }
}

// ---------------- kernel 1: parallel target encode (1 block, 800 threads) ---
// One thread per (b,t). JAX wrap semantics:
//  * padded rows -> mask cell (b, 0, 0, WW-1), tx=ty=0, tw=th=log(1e-16), cls 0
//  * noobj scatter: anchors failing iou>thr (or invalid) wrap to anchor 2
// Dedupe: ignore set via idempotent bitmap atomicOr; mask cells via smem hash
// (CAS insert, atomicMax(t) for last-wins, atomicOr for class bits).
__global__ void k_encode(const float* __restrict__ annot) {
    __shared__ int          s_key[TBL];
    __shared__ int          s_prio[TBL];
    __shared__ unsigned int s_cls[TBL*3];
    __shared__ int          s_rec[TBL];
    __shared__ int          s_cnt;

    int tid = threadIdx.x;
    for (int i = tid; i < TBL; i += blockDim.x) {
        s_key[i] = -1; s_prio[i] = -1;
        s_cls[i*3] = 0u; s_cls[i*3+1] = 0u; s_cls[i*3+2] = 0u;
    }
    for (int i = tid; i < NBITW; i += blockDim.x) g_ign[i] = 0u;
    if (tid == 0) {
        s_cnt = 0;
        g_acc[0] = 0.0; g_acc[1] = 0.0; g_acc[2] = 0.0;
        g_done = 0u;
    }
    __syncthreads();

    int slot = -1, myt = -1;
    float vtx = 0.f, vty = 0.f, vtw = 0.f, vth = 0.f;

    if (tid < BB * TT) {
        int b = tid / TT, t = tid - b * TT;
        const float* an = annot + tid * 5;
        float a0 = an[0], a1 = an[1], a2 = an[2], a3 = an[3], a4 = an[4];
        bool valid = (a0 + a1 + a2 + a3 + a4) != 0.0f;

        float gx = a1 * (float)WW, gy = a2 * (float)HH;
        float gw = a3 * (float)WW, gh = a4 * (float)HH;
        int gi = (int)floorf(gx), gj = (int)floorf(gy);

        float ious[3];
        float best = -1.0f; int bn = 0;
        const float eps = 1e-9f;
        #pragma unroll
        for (int a = 0; a < 3; ++a) {
            float inter = fminf(gw, c_aw[a]) * fminf(gh, c_ah[a]);
            float un = gw * (gh + eps) + c_aw[a] * (c_ah[a] + eps) - inter + eps;
            float iou = inter / un;
            ious[a] = iou;
            if (iou > best) { best = iou; bn = a; }   // first max
        }

        // ignore bits (wrap failing anchors to AA-1 = 2)
        if (gi >= 0 && gi < WW && gj >= 0 && gj < HH) {
            #pragma unroll
            for (int a = 0; a < 3; ++a) {
                bool cond = (ious[a] > IGNORE_THR) && valid;
                int ae = cond ? a : (AA - 1);
                int c = ((b * AA + ae) * HH + gj) * WW + gi;
                atomicOr(&g_ign[c >> 5], 1u << (c & 31));
            }
        }

        // mask record (gi wraps to WW-1 when invalid)
        int ii = valid ? gi : (WW - 1);
        if (ii >= 0 && ii < WW && gj >= 0 && gj < HH) {
            int cell = ((b * AA + bn) * HH + gj) * WW + ii;
            unsigned int h = ((unsigned int)cell * 2654435761u) >> 21; // 11 bits
            int j = (int)h & TBLM;
            while (true) {
                int old = atomicCAS(&s_key[j], -1, cell);
                if (old == -1) {
                    int r = atomicAdd(&s_cnt, 1);
                    s_rec[j] = r;
                    g_rcell[r] = cell;
                    break;
                }
                if (old == cell) break;
                j = (j + 1) & TBLM;
            }
            atomicMax(&s_prio[j], t);
            int ci = (int)a0;
            if (ci >= 0 && ci < NCLS)
                atomicOr(&s_cls[j*3 + (ci >> 5)], 1u << (ci & 31));
            slot = j; myt = t;
            vtx = gx - (float)gi;
            vty = gy - (float)gj;
            vtw = logf(gw / c_aw[bn] + 1e-16f);
            vth = logf(gh / c_ah[bn] + 1e-16f);
        }
    }
    __syncthreads();

    // unique last-wins winner per cell writes the record
    if (slot >= 0 && s_prio[slot] == myt) {
        int r = s_rec[slot];
        g_rtx[r] = vtx; g_rty[r] = vty; g_rtw[r] = vtw; g_rth[r] = vth;
        g_rtcls[r*3+0] = s_cls[slot*3+0];
        g_rtcls[r*3+1] = s_cls[slot*3+1];
        g_rtcls[r*3+2] = s_cls[slot*3+2];
    }
    if (tid == 0) g_npos = s_cnt;
}

// ---------------- kernel 2: fused reduce + finalize --------------------------
__global__ void k_main(const float* __restrict__ pred,
                       float* __restrict__ out, int out_n) {
    if (blockIdx.x < DENSE_BLOCKS) {
        // sum sp(conf) over all NON-ignored cells -> g_acc[0]
        int tid = blockIdx.x * blockDim.x + threadIdx.x;
        double s = 0.0;
        if (tid < NV) {
            const int V_ROW = HWX / 4;                 // 1444
            int r = tid / V_ROW;
            int v = tid - r * V_ROW;
            int b = r / AA, a = r - b * AA;
            const float4 f = *reinterpret_cast<const float4*>(
                pred + (size_t)b * PRED_B + (size_t)(a * ATTR + 4) * HWX + 4 * v);
            int cbase = r * HWX + 4 * v;
            unsigned int bits = g_ign[cbase >> 5] >> (cbase & 31);
            if (!(bits & 1u)) s += (double)sp(f.x);
            if (!(bits & 2u)) s += (double)sp(f.y);
            if (!(bits & 4u)) s += (double)sp(f.z);
            if (!(bits & 8u)) s += (double)sp(f.w);
        }
        blk_atomic(s, &g_acc[0]);
    } else {
        // one warp per mask record -> g_acc[1] (obj), g_acc[2] (cls)
        int widx = (blockIdx.x - DENSE_BLOCKS) * 8 + (threadIdx.x >> 5);
        int lane = threadIdx.x & 31;
        double lcls = 0.0, lobj = 0.0;

        if (widx < g_npos) {
            int cell = g_rcell[widx];
            int pix = cell % HWX;
            int ra = cell / HWX;                       // b*AA + a
            int b = ra / AA, a = ra - b * AA;
            const float* base = pred + (size_t)b * PRED_B + (size_t)(a * ATTR) * HWX;

            unsigned int cb0 = g_rtcls[widx*3+0];
            unsigned int cb1 = g_rtcls[widx*3+1];
            unsigned int cb2 = g_rtcls[widx*3+2];
            #pragma unroll
            for (int q = 0; q < 3; ++q) {
                int c = lane + 32 * q;
                if (c < NCLS) {
                    float z = base[(size_t)(5 + c) * HWX + pix];
                    unsigned int w = (q == 0) ? cb0 : (q == 1) ? cb1 : cb2;
                    bool tgt = (w >> (c & 31)) & 1u;
                    lcls += (double)(tgt ? sp(-z) : sp(z));
                }
            }
            if (lane == 0) {
                float zx = base[(size_t)0 * HWX + pix];
                float zy = base[(size_t)1 * HWX + pix];
                float zw = base[(size_t)2 * HWX + pix];
                float zh = base[(size_t)3 * HWX + pix];
                float zc = base[(size_t)4 * HWX + pix];
                float tx = g_rtx[widx], ty = g_rty[widx];
                float tw = g_rtw[widx], th = g_rth[widx];
                double lxy = (double)(tx * sp(-zx) + (1.0f - tx) * sp(zx))
                           + (double)(ty * sp(-zy) + (1.0f - ty) * sp(zy));
                double lwh = (double)((zw - tw) * (zw - tw) + (zh - th) * (zh - th));
                lobj = 0.5 * lxy + 2.5 * lwh + (double)sp(-zc);
            }
        }
        blk_atomic(lcls, &g_acc[2]);
        __syncthreads();
        blk_atomic(lobj, &g_acc[1]);
    }

    // last-block finalize
    if (threadIdx.x == 0) {
        __threadfence();
        unsigned int prev = atomicAdd(&g_done, 1u);
        if (prev == (unsigned int)(TOTAL_BLOCKS - 1)) {
            const double Nd = (double)NCELL;
            double loss = (0.5 * g_acc[0] + g_acc[1]) / Nd
                        + g_acc[2] / ((double)g_npos * (double)NCLS);
            float v = (float)loss;
            for (int i = 0; i < out_n; ++i) out[i] = v;
        }
    }
}

extern "C" void kernel_launch(void* const* d_in, const int* in_sizes, int n_in,
                              void* d_out, int out_size) {
    // autodetect input order by element count (pred = 23.5M, annot = 4000)
    const float* pred;
    const float* annot;
    if (n_in >= 2 && in_sizes[1] > in_sizes[0]) {
        pred  = (const float*)d_in[1];
        annot = (const float*)d_in[0];
    } else {
        pred  = (const float*)d_in[0];
        annot = (const float*)d_in[1];
    }
    float* out = (float*)d_out;

    k_encode<<<1, BB*TT>>>(annot);
    k_main<<<TOTAL_BLOCKS, 256>>>(pred, out, out_size);
}